// round 1
// baseline (speedup 1.0000x reference)
#include <cuda_runtime.h>
#include <math_constants.h>

// ---------------------------------------------------------------------------
// Problem constants
// ---------------------------------------------------------------------------
#define NB   2048        // sequence length
#define HID  1024
#define NH   16          // heads
#define DH   64          // head dim
#define WKW  64          // WK
#define WVW  64          // WV
#define NSLOT 129        // 2*WK+1

// ---------------------------------------------------------------------------
// Device scratch (allocation-free rule: __device__ globals)
// ---------------------------------------------------------------------------
__device__ float g_Q[NH * NB * DH];      // [h][n][d]
__device__ float g_K[NH * NB * DH];
__device__ float g_V[NH * NB * DH];
__device__ float g_Ak[NH * NB * NSLOT]; // relative-K bias table [h][n][slot]
__device__ float g_WrvT[DH * NSLOT];    // W_rel_v transposed: [d][w]

// ---------------------------------------------------------------------------
// QKV projection: Y = X @ W + b, output in head-major [h][n][d]
// 128x128 block tile, K-step 8, 256 threads, 8x8 per thread
// ---------------------------------------------------------------------------
__global__ __launch_bounds__(256) void qkv_gemm(
    const float* __restrict__ X,
    const float* __restrict__ Wq, const float* __restrict__ bq,
    const float* __restrict__ Wk, const float* __restrict__ bk,
    const float* __restrict__ Wv, const float* __restrict__ bv)
{
    const float* W;
    const float* bias;
    float* out;
    if (blockIdx.z == 0)      { W = Wq; bias = bq; out = g_Q; }
    else if (blockIdx.z == 1) { W = Wk; bias = bk; out = g_K; }
    else                      { W = Wv; bias = bv; out = g_V; }

    __shared__ float As[8][128];
    __shared__ float Bs[8][128];

    const int tid = threadIdx.x;
    const int bm = blockIdx.y * 128;
    const int bn = blockIdx.x * 128;
    const int tx = tid & 15;        // 0..15
    const int ty = tid >> 4;        // 0..15

    const int la_m = tid >> 1;          // 0..127
    const int la_k = (tid & 1) * 4;     // 0 or 4
    const int lb_k = tid >> 5;          // 0..7
    const int lb_n = (tid & 31) * 4;    // 0..124

    float acc[8][8];
#pragma unroll
    for (int a = 0; a < 8; a++)
#pragma unroll
        for (int b = 0; b < 8; b++) acc[a][b] = 0.f;

    for (int kk = 0; kk < HID; kk += 8) {
        float4 a4 = *(const float4*)(X + (size_t)(bm + la_m) * HID + kk + la_k);
        float4 b4 = *(const float4*)(W + (size_t)(kk + lb_k) * HID + bn + lb_n);
        __syncthreads();
        As[la_k + 0][la_m] = a4.x;
        As[la_k + 1][la_m] = a4.y;
        As[la_k + 2][la_m] = a4.z;
        As[la_k + 3][la_m] = a4.w;
        *(float4*)&Bs[lb_k][lb_n] = b4;
        __syncthreads();
#pragma unroll
        for (int k = 0; k < 8; k++) {
            float ar[8], br[8];
            float4 t0 = *(const float4*)&As[k][ty * 8];
            float4 t1 = *(const float4*)&As[k][ty * 8 + 4];
            ar[0]=t0.x; ar[1]=t0.y; ar[2]=t0.z; ar[3]=t0.w;
            ar[4]=t1.x; ar[5]=t1.y; ar[6]=t1.z; ar[7]=t1.w;
            float4 u0 = *(const float4*)&Bs[k][tx * 8];
            float4 u1 = *(const float4*)&Bs[k][tx * 8 + 4];
            br[0]=u0.x; br[1]=u0.y; br[2]=u0.z; br[3]=u0.w;
            br[4]=u1.x; br[5]=u1.y; br[6]=u1.z; br[7]=u1.w;
#pragma unroll
            for (int a = 0; a < 8; a++)
#pragma unroll
                for (int b = 0; b < 8; b++)
                    acc[a][b] = fmaf(ar[a], br[b], acc[a][b]);
        }
    }

#pragma unroll
    for (int a = 0; a < 8; a++) {
        const int row = bm + ty * 8 + a;
#pragma unroll
        for (int b = 0; b < 8; b++) {
            const int col = bn + tx * 8 + b;
            const float v = acc[a][b] + bias[col];
            // head-major: [h][n][d]
            out[((size_t)(col >> 6) * NB + row) * DH + (col & 63)] = v;
        }
    }
}

// ---------------------------------------------------------------------------
// a_k[h][i][w] = sum_d Q[h][i][d] * W_rel_k[d][w]
// ---------------------------------------------------------------------------
__global__ void ak_kernel(const float* __restrict__ Wrk)
{
    const int i = blockIdx.x;
    const int h = blockIdx.y;
    const int w = threadIdx.x;
    if (w >= NSLOT) return;
    const float* Qr = g_Q + ((size_t)h * NB + i) * DH;
    float s = 0.f;
#pragma unroll
    for (int d = 0; d < DH; d++)
        s = fmaf(Qr[d], Wrk[d * NSLOT + w], s);
    g_Ak[((size_t)h * NB + i) * NSLOT + w] = s;
}

// ---------------------------------------------------------------------------
// Transpose W_rel_v [w][d] -> [d][w]
// ---------------------------------------------------------------------------
__global__ void wrvt_kernel(const float* __restrict__ Wrv)
{
    const int idx = blockIdx.x * 256 + threadIdx.x;
    if (idx < NSLOT * DH) {
        const int w = idx / DH;
        const int d = idx % DH;
        g_WrvT[d * NSLOT + w] = Wrv[idx];
    }
}

// ---------------------------------------------------------------------------
// Fused flash attention with relative-position K bias + banded V contribution.
// 1 thread = 1 query row. Block = 128 rows of one head.
// ---------------------------------------------------------------------------
__global__ __launch_bounds__(128) void attn_kernel(
    const float* __restrict__ mask, float* __restrict__ out)
{
    __shared__ float sK[32][64];
    __shared__ float sV[32][64];
    __shared__ float sExt[32];

    const int h = blockIdx.y;
    const int i = blockIdx.x * 128 + threadIdx.x;   // query row
    const int tid = threadIdx.x;

    // Load q row into registers
    float q[64];
    {
        const float* Qr = g_Q + ((size_t)h * NB + i) * DH;
#pragma unroll
        for (int d4 = 0; d4 < 16; d4++) {
            float4 t = *(const float4*)(Qr + d4 * 4);
            q[4*d4+0]=t.x; q[4*d4+1]=t.y; q[4*d4+2]=t.z; q[4*d4+3]=t.w;
        }
    }

    float acc[64];
#pragma unroll
    for (int d = 0; d < 64; d++) acc[d] = 0.f;
    float m = -3.4028235e38f;
    float l = 0.f;

    float bandS[NSLOT];   // raw scores of in-band keys (local mem), replayed in epilogue

    const float* Ak = g_Ak + ((size_t)h * NB + i) * NSLOT;
    const float* Kg = g_K + (size_t)h * NB * DH;
    const float* Vg = g_V + (size_t)h * NB * DH;

#pragma unroll 1
    for (int kt = 0; kt < NB; kt += 32) {
        __syncthreads();
        // cooperative tile load: 32 keys x 64 dims (2048 floats each) = 4 float4/thread
        {
            const float4* ksrc = (const float4*)(Kg + (size_t)kt * DH);
            const float4* vsrc = (const float4*)(Vg + (size_t)kt * DH);
            float4* kdst = (float4*)&sK[0][0];
            float4* vdst = (float4*)&sV[0][0];
#pragma unroll
            for (int r = 0; r < 4; r++) {
                const int f = r * 128 + tid;
                kdst[f] = ksrc[f];
                vdst[f] = vsrc[f];
            }
            if (tid < 32)
                sExt[tid] = (1.0f - mask[kt + tid]) * (-3.4028235e38f);
        }
        __syncthreads();

#pragma unroll 1
        for (int jc = 0; jc < 32; jc += 8) {
            float s[8];
#pragma unroll
            for (int jj = 0; jj < 8; jj++) {
                const int j = jc + jj;
                const float4* kr = (const float4*)&sK[j][0];
                float sum = 0.f;
#pragma unroll
                for (int d4 = 0; d4 < 16; d4++) {
                    float4 kk = kr[d4];
                    sum = fmaf(q[4*d4+0], kk.x, sum);
                    sum = fmaf(q[4*d4+1], kk.y, sum);
                    sum = fmaf(q[4*d4+2], kk.z, sum);
                    sum = fmaf(q[4*d4+3], kk.w, sum);
                }
                const int slot = kt + j - i + WKW;
                const bool inb = (unsigned)slot <= 128u;
                if (inb) sum += Ak[slot];
                float sv = sum * 0.125f + sExt[j];
                if (inb) bandS[slot] = sv;
                s[jj] = sv;
            }
            float tm = s[0];
#pragma unroll
            for (int jj = 1; jj < 8; jj++) tm = fmaxf(tm, s[jj]);
            const float mnew = fmaxf(m, tm);
            if (mnew > m) {
                const float sc = __expf(m - mnew);
                l *= sc;
#pragma unroll
                for (int d = 0; d < 64; d++) acc[d] *= sc;
                m = mnew;
            }
#pragma unroll
            for (int jj = 0; jj < 8; jj++) {
                const float p = __expf(s[jj] - m);
                l += p;
                const float4* vr = (const float4*)&sV[jc + jj][0];
#pragma unroll
                for (int d4 = 0; d4 < 16; d4++) {
                    float4 vv = vr[d4];
                    acc[4*d4+0] = fmaf(p, vv.x, acc[4*d4+0]);
                    acc[4*d4+1] = fmaf(p, vv.y, acc[4*d4+1]);
                    acc[4*d4+2] = fmaf(p, vv.z, acc[4*d4+2]);
                    acc[4*d4+3] = fmaf(p, vv.w, acc[4*d4+3]);
                }
            }
        }
    }

    // Band epilogue: ctx += probs_band @ W_rel_v (unnormalized; divided by l below)
    {
        const int wlo = (i < WVW) ? (WVW - i) : 0;
        const int whi = (i > NB - 1 - WVW) ? (NB - 1 - i + WVW) : (2 * WVW);
#pragma unroll 1
        for (int w = wlo; w <= whi; w++) {
            const float p = __expf(bandS[w] - m);
            const float* wr = g_WrvT + w;
#pragma unroll
            for (int d = 0; d < 64; d++)
                acc[d] = fmaf(p, __ldg(wr + d * NSLOT), acc[d]);
        }
    }

    const float invl = 1.0f / l;
    float* orow = out + (size_t)i * HID + h * DH;
#pragma unroll
    for (int d4 = 0; d4 < 16; d4++) {
        float4 o;
        o.x = acc[4*d4+0] * invl;
        o.y = acc[4*d4+1] * invl;
        o.z = acc[4*d4+2] * invl;
        o.w = acc[4*d4+3] * invl;
        *(float4*)(orow + 4 * d4) = o;
    }
}

// ---------------------------------------------------------------------------
// Launch
// ---------------------------------------------------------------------------
extern "C" void kernel_launch(void* const* d_in, const int* in_sizes, int n_in,
                              void* d_out, int out_size)
{
    const float* X    = (const float*)d_in[0];
    const float* mask = (const float*)d_in[1];
    const float* Wq   = (const float*)d_in[2];
    const float* bq   = (const float*)d_in[3];
    const float* Wk   = (const float*)d_in[4];
    const float* bk   = (const float*)d_in[5];
    const float* Wv   = (const float*)d_in[6];
    const float* bv   = (const float*)d_in[7];
    const float* Wrk  = (const float*)d_in[8];
    const float* Wrv  = (const float*)d_in[9];
    float* out = (float*)d_out;

    dim3 gg(HID / 128, NB / 128, 3);
    qkv_gemm<<<gg, 256>>>(X, Wq, bq, Wk, bk, Wv, bv);

    ak_kernel<<<dim3(NB, NH), 160>>>(Wrk);
    wrvt_kernel<<<(NSLOT * DH + 255) / 256, 256>>>(Wrv);

    attn_kernel<<<dim3(NB / 128, NH), 128>>>(mask, out);
}